// round 8
// baseline (speedup 1.0000x reference)
#include <cuda_runtime.h>
#include <cuda_bf16.h>
#include <cstdint>

#define HID 128
#define N_MAX 400000
__device__ float g_M[(size_t)N_MAX * HID];

// Pre-split weights in padded-panel layout: panel p holds k in [32p,32p+32),
// row = n (0..127), row stride 80 bytes (64B data + 16B pad -> conflict-free
// ldmatrix: (r*20)%32 = {0,20,8,28,16,4,24,12}, perfect 4-bank partition).
// offset = p*10240 + n*80 + (k%32)*2
__device__ __align__(16) unsigned char g_Bhe[30720];   // edge W_i hi (3 panels, k<80 valid, k80-95 zero)
__device__ __align__(16) unsigned char g_Ble[30720];   // edge W_i lo
__device__ __align__(16) unsigned char g_Bhn[61440];   // node W_o hi (6 panels, K=192)
__device__ __align__(16) unsigned char g_Bln[61440];   // node W_o lo

// ---------------------------------------------------------------------------
// helpers
// ---------------------------------------------------------------------------
__device__ __forceinline__ uint32_t smem_u32(const void* p) {
    uint32_t a;
    asm("{ .reg .u64 t; cvta.to.shared.u64 t, %1; cvt.u32.u64 %0, t; }" : "=r"(a) : "l"(p));
    return a;
}
__device__ __forceinline__ void ldm4(uint32_t* r, uint32_t addr) {
    asm volatile("ldmatrix.sync.aligned.m8n8.x4.shared.b16 {%0,%1,%2,%3}, [%4];"
                 : "=r"(r[0]), "=r"(r[1]), "=r"(r[2]), "=r"(r[3]) : "r"(addr));
}
__device__ __forceinline__ void mma16816(float* c, const uint32_t* a, uint32_t b0, uint32_t b1) {
    asm volatile("mma.sync.aligned.m16n8k16.row.col.f32.bf16.bf16.f32 "
                 "{%0,%1,%2,%3}, {%4,%5,%6,%7}, {%8,%9}, {%0,%1,%2,%3};"
                 : "+f"(c[0]), "+f"(c[1]), "+f"(c[2]), "+f"(c[3])
                 : "r"(a[0]), "r"(a[1]), "r"(a[2]), "r"(a[3]), "r"(b0), "r"(b1));
}
__device__ __forceinline__ void red_add_v4(float* p, float a, float b, float c, float d) {
    asm volatile("red.global.add.v4.f32 [%0], {%1,%2,%3,%4};"
                 :: "l"(p), "f"(a), "f"(b), "f"(c), "f"(d) : "memory");
}
// bf16 split of a float pair -> packed hi (bf16x2) and lo (bf16x2), mem order [va,vb]
__device__ __forceinline__ void split2(float va, float vb, uint32_t& hi, uint32_t& lo) {
    uint32_t h;
    asm("cvt.rn.bf16x2.f32 %0, %1, %2;" : "=r"(h) : "f"(vb), "f"(va));
    float ha = __uint_as_float(h << 16);
    float hb = __uint_as_float(h & 0xFFFF0000u);
    float la = va - ha, lb = vb - hb;
    uint32_t l;
    asm("cvt.rn.bf16x2.f32 %0, %1, %2;" : "=r"(l) : "f"(lb), "f"(la));
    hi = h; lo = l;
}

#define PBYTES 10240
#define RSTR   80

// ---------------------------------------------------------------------------
// Kernel P: split + transpose + panel-layout the weights
// ---------------------------------------------------------------------------
__global__ void k_prep(const float* __restrict__ Wi, const float* __restrict__ Wo) {
    int t = blockIdx.x * blockDim.x + threadIdx.x;
    if (t < 128 * 96) {
        int n = t / 96, k = t % 96;
        float v = (k < 80) ? Wi[k * 128 + n] : 0.f;
        __nv_bfloat16 hb = __float2bfloat16(v);
        __nv_bfloat16 lb = __float2bfloat16(v - __bfloat162float(hb));
        uint32_t off = (uint32_t)(k >> 5) * PBYTES + (uint32_t)n * RSTR + (k & 31) * 2;
        *(__nv_bfloat16*)(g_Bhe + off) = hb;
        *(__nv_bfloat16*)(g_Ble + off) = lb;
    }
    int t2 = t - 128 * 96;
    if (t2 >= 0 && t2 < 128 * 192) {
        int n = t2 / 192, k = t2 % 192;
        float v = Wo[k * 128 + n];
        __nv_bfloat16 hb = __float2bfloat16(v);
        __nv_bfloat16 lb = __float2bfloat16(v - __bfloat162float(hb));
        uint32_t off = (uint32_t)(k >> 5) * PBYTES + (uint32_t)n * RSTR + (k & 31) * 2;
        *(__nv_bfloat16*)(g_Bhn + off) = hb;
        *(__nv_bfloat16*)(g_Bln + off) = lb;
    }
}

// ---------------------------------------------------------------------------
// Kernel 0: zero the message buffer
// ---------------------------------------------------------------------------
__global__ void k_zero(int n4) {
    int i = blockIdx.x * blockDim.x + threadIdx.x;
    if (i < n4) ((float4*)g_M)[i] = make_float4(0.f, 0.f, 0.f, 0.f);
}

// ---------------------------------------------------------------------------
// Kernel 1: edges. h0 = relu([x[src]|ea] @ W_i + b_i) via HMMA, scatter to M.
// Tile 128 edges x 128 cols, K=80 (3 panels of 32, last half-zero). 8 warps.
// ---------------------------------------------------------------------------
#define EA_HI   0
#define EA_LO   30720
#define EB_HI   61440
#define EB_LO   92160
#define E_SDST  122880
#define E_SBIAS 123392
#define E_SMEM  123904

__global__ __launch_bounds__(256, 1) void k_edge(
    const float* __restrict__ x,
    const int*   __restrict__ src,
    const int*   __restrict__ dst,
    const float* __restrict__ ea,
    const float* __restrict__ bi,
    int E)
{
    extern __shared__ char smem[];
    const uint32_t sb = smem_u32(smem);
    const int tid = threadIdx.x;
    const int e0 = blockIdx.x * 128;

    // ---- stage A (gather + bf16 split into panels) ----
    {
        const int row = tid & 127, hf = tid >> 7;
        int e = e0 + row;
        int ec = (e < E) ? e : (E - 1);
        int s = src[ec];
        uint32_t rbase = (uint32_t)row * RSTR;
        uint32_t hi, lo;
        if (hf == 0) {
            const float4* xr = (const float4*)(x + (size_t)s * 64);
            #pragma unroll
            for (int j = 0; j < 10; j++) {
                float4 v = xr[j];
                int k0 = j * 4;
                uint32_t off = (uint32_t)(k0 >> 5) * PBYTES + rbase + (k0 & 31) * 2;
                split2(v.x, v.y, hi, lo);
                *(uint32_t*)(smem + EA_HI + off) = hi; *(uint32_t*)(smem + EA_LO + off) = lo;
                split2(v.z, v.w, hi, lo);
                *(uint32_t*)(smem + EA_HI + off + 4) = hi; *(uint32_t*)(smem + EA_LO + off + 4) = lo;
            }
        } else {
            const float4* xr = (const float4*)(x + (size_t)s * 64 + 40);
            #pragma unroll
            for (int j = 0; j < 6; j++) {
                float4 v = xr[j];
                int k0 = 40 + j * 4;
                uint32_t off = (uint32_t)(k0 >> 5) * PBYTES + rbase + (k0 & 31) * 2;
                split2(v.x, v.y, hi, lo);
                *(uint32_t*)(smem + EA_HI + off) = hi; *(uint32_t*)(smem + EA_LO + off) = lo;
                split2(v.z, v.w, hi, lo);
                *(uint32_t*)(smem + EA_HI + off + 4) = hi; *(uint32_t*)(smem + EA_LO + off + 4) = lo;
            }
            const float4* er = (const float4*)(ea + (size_t)ec * 16);
            #pragma unroll
            for (int j = 0; j < 4; j++) {
                float4 v = er[j];
                int k0 = 64 + j * 4;
                uint32_t off = 2 * PBYTES + rbase + (k0 & 31) * 2;
                split2(v.x, v.y, hi, lo);
                *(uint32_t*)(smem + EA_HI + off) = hi; *(uint32_t*)(smem + EA_LO + off) = lo;
                split2(v.z, v.w, hi, lo);
                *(uint32_t*)(smem + EA_HI + off + 4) = hi; *(uint32_t*)(smem + EA_LO + off + 4) = lo;
            }
        }
        // zero pad k=80..95 region of panel 2
        if (tid < 128) {
            uint32_t zb = 2 * PBYTES + (uint32_t)tid * RSTR + 32;
            #pragma unroll
            for (int i = 0; i < 8; i++) {
                *(uint32_t*)(smem + EA_HI + zb + i * 4) = 0;
                *(uint32_t*)(smem + EA_LO + zb + i * 4) = 0;
            }
            int e2 = e0 + tid;
            ((int*)(smem + E_SDST))[tid] = dst[(e2 < E) ? e2 : (E - 1)];
            ((float*)(smem + E_SBIAS))[tid] = bi[tid];
        }
        // ---- stage B (bulk copy, 1920 float4 per term) ----
        #pragma unroll
        for (int i = 0; i < 8; i++) {
            int idx = tid + i * 256;
            if (idx < 1920) {
                ((float4*)(smem + EB_HI))[idx] = ((const float4*)g_Bhe)[idx];
                ((float4*)(smem + EB_LO))[idx] = ((const float4*)g_Ble)[idx];
            }
        }
    }
    __syncthreads();

    // ---- HMMA mainloop ----
    const int l = tid & 31, w = tid >> 5;
    const uint32_t aoff = sb + (uint32_t)(w * 16 + ((l >> 3) & 1) * 8 + (l & 7)) * RSTR + ((l >> 4) << 4);
    const uint32_t boff = sb + (uint32_t)(((l >> 4) << 3) + (l & 7)) * RSTR + (((l >> 3) & 1) << 4);

    float acc[64];
    #pragma unroll
    for (int i = 0; i < 64; i++) acc[i] = 0.f;

    #pragma unroll
    for (int p = 0; p < 3; p++) {
        uint32_t ah0[4], ah1[4], al0[4], al1[4];
        uint32_t ap = aoff + p * PBYTES;
        ldm4(ah0, ap + EA_HI);      ldm4(ah1, ap + EA_HI + 32);
        ldm4(al0, ap + EA_LO);      ldm4(al1, ap + EA_LO + 32);
        #pragma unroll
        for (int g = 0; g < 8; g++) {
            uint32_t bp = boff + p * PBYTES + g * (16 * RSTR);
            uint32_t bh0[4], bh1[4], bl0[4], bl1[4];
            ldm4(bh0, bp + EB_HI);  ldm4(bh1, bp + EB_HI + 32);
            ldm4(bl0, bp + EB_LO);  ldm4(bl1, bp + EB_LO + 32);
            float* c0 = acc + g * 8;
            float* c1 = acc + g * 8 + 4;
            mma16816(c0, ah0, bh0[0], bh0[1]); mma16816(c1, ah0, bh0[2], bh0[3]);
            mma16816(c0, ah1, bh1[0], bh1[1]); mma16816(c1, ah1, bh1[2], bh1[3]);
            mma16816(c0, ah0, bl0[0], bl0[1]); mma16816(c1, ah0, bl0[2], bl0[3]);
            mma16816(c0, ah1, bl1[0], bl1[1]); mma16816(c1, ah1, bl1[2], bl1[3]);
            mma16816(c0, al0, bh0[0], bh0[1]); mma16816(c1, al0, bh0[2], bh0[3]);
            mma16816(c0, al1, bh1[0], bh1[1]); mma16816(c1, al1, bh1[2], bh1[3]);
        }
    }

    // ---- epilogue: bias + relu + pair-exchange -> red.v4 scatter ----
    {
        const int rowA = w * 16 + (l >> 2);
        const int rowB = rowA + 8;
        const int dA = ((const int*)(smem + E_SDST))[rowA];
        const int dB = ((const int*)(smem + E_SDST))[rowB];
        const bool doA = (e0 + rowA) < E, doB = (e0 + rowB) < E;
        const float* sbias = (const float*)(smem + E_SBIAS);
        #pragma unroll
        for (int G = 0; G < 16; G++) {
            int c0 = G * 8 + (l & 3) * 2;
            float b0 = sbias[c0], b1 = sbias[c0 + 1];
            float v0 = fmaxf(acc[G * 4 + 0] + b0, 0.f);
            float v1 = fmaxf(acc[G * 4 + 1] + b1, 0.f);
            float v2 = fmaxf(acc[G * 4 + 2] + b0, 0.f);
            float v3 = fmaxf(acc[G * 4 + 3] + b1, 0.f);
            float u0 = __shfl_xor_sync(~0u, v0, 1);
            float u1 = __shfl_xor_sync(~0u, v1, 1);
            float u2 = __shfl_xor_sync(~0u, v2, 1);
            float u3 = __shfl_xor_sync(~0u, v3, 1);
            int cb = G * 8 + ((l & 2) << 1);
            if (!(l & 1)) {
                if (doA) red_add_v4(g_M + (size_t)dA * HID + cb, v0, v1, u0, u1);
            } else {
                if (doB) red_add_v4(g_M + (size_t)dB * HID + cb, u2, u3, v2, v3);
            }
        }
    }
}

// ---------------------------------------------------------------------------
// Kernel 2: nodes. out = relu([x|M] @ W_o + b_o) via HMMA.
// Tile 128 nodes x 128 cols, K=192 in two phases of 96 (3 panels each).
// ---------------------------------------------------------------------------
#define NA_HI   0
#define NA_LO   30720
#define NB_HI   61440
#define NB_LO   92160
#define N_SBIAS 122880
#define N_SMEM  123392

__global__ __launch_bounds__(256, 1) void k_node(
    const float* __restrict__ x,
    const float* __restrict__ bo,
    float*       __restrict__ out,
    int N)
{
    extern __shared__ char smem[];
    const uint32_t sb = smem_u32(smem);
    const int tid = threadIdx.x;
    const int n0 = blockIdx.x * 128;

    const int l = tid & 31, w = tid >> 5;
    const uint32_t aoff = sb + (uint32_t)(w * 16 + ((l >> 3) & 1) * 8 + (l & 7)) * RSTR + ((l >> 4) << 4);
    const uint32_t boff = sb + (uint32_t)(((l >> 4) << 3) + (l & 7)) * RSTR + (((l >> 3) & 1) << 4);

    float acc[64];
    #pragma unroll
    for (int i = 0; i < 64; i++) acc[i] = 0.f;

    const int row = tid & 127, hf = tid >> 7;
    int n = n0 + row;
    int nc = (n < N) ? n : (N - 1);
    const uint32_t rbase = (uint32_t)row * RSTR;

    if (tid < 128) ((float*)(smem + N_SBIAS))[tid] = bo[tid];

    #pragma unroll
    for (int ph = 0; ph < 2; ph++) {
        if (ph) __syncthreads();   // previous compute done before restage
        // ---- stage A phase ----
        {
            uint32_t hi, lo;
            if (ph == 0) {
                if (hf == 0) {
                    const float4* xr = (const float4*)(x + (size_t)nc * 64);
                    #pragma unroll
                    for (int j = 0; j < 16; j++) {
                        float4 v = xr[j];
                        int k0 = j * 4;
                        uint32_t off = (uint32_t)(k0 >> 5) * PBYTES + rbase + (k0 & 31) * 2;
                        split2(v.x, v.y, hi, lo);
                        *(uint32_t*)(smem + NA_HI + off) = hi; *(uint32_t*)(smem + NA_LO + off) = lo;
                        split2(v.z, v.w, hi, lo);
                        *(uint32_t*)(smem + NA_HI + off + 4) = hi; *(uint32_t*)(smem + NA_LO + off + 4) = lo;
                    }
                } else {
                    const float4* mr = (const float4*)(g_M + (size_t)nc * HID);
                    #pragma unroll
                    for (int j = 0; j < 8; j++) {
                        float4 v = mr[j];
                        int k0 = 64 + j * 4;
                        uint32_t off = (uint32_t)(k0 >> 5) * PBYTES + rbase + (k0 & 31) * 2;
                        split2(v.x, v.y, hi, lo);
                        *(uint32_t*)(smem + NA_HI + off) = hi; *(uint32_t*)(smem + NA_LO + off) = lo;
                        split2(v.z, v.w, hi, lo);
                        *(uint32_t*)(smem + NA_HI + off + 4) = hi; *(uint32_t*)(smem + NA_LO + off + 4) = lo;
                    }
                }
            } else {
                if (hf == 0) {
                    const float4* mr = (const float4*)(g_M + (size_t)nc * HID + 32);
                    #pragma unroll
                    for (int j = 0; j < 16; j++) {
                        float4 v = mr[j];
                        int k0 = 96 + j * 4;
                        uint32_t off = (uint32_t)((k0 - 96) >> 5) * PBYTES + rbase + (k0 & 31) * 2;
                        split2(v.x, v.y, hi, lo);
                        *(uint32_t*)(smem + NA_HI + off) = hi; *(uint32_t*)(smem + NA_LO + off) = lo;
                        split2(v.z, v.w, hi, lo);
                        *(uint32_t*)(smem + NA_HI + off + 4) = hi; *(uint32_t*)(smem + NA_LO + off + 4) = lo;
                    }
                } else {
                    const float4* mr = (const float4*)(g_M + (size_t)nc * HID + 96);
                    #pragma unroll
                    for (int j = 0; j < 8; j++) {
                        float4 v = mr[j];
                        int k0 = 160 + j * 4;
                        uint32_t off = (uint32_t)((k0 - 96) >> 5) * PBYTES + rbase + (k0 & 31) * 2;
                        split2(v.x, v.y, hi, lo);
                        *(uint32_t*)(smem + NA_HI + off) = hi; *(uint32_t*)(smem + NA_LO + off) = lo;
                        split2(v.z, v.w, hi, lo);
                        *(uint32_t*)(smem + NA_HI + off + 4) = hi; *(uint32_t*)(smem + NA_LO + off + 4) = lo;
                    }
                }
            }
            // ---- stage B phase (1920 float4 per term) ----
            const float4* bh = (const float4*)(g_Bhn + ph * 30720);
            const float4* bl = (const float4*)(g_Bln + ph * 30720);
            #pragma unroll
            for (int i = 0; i < 8; i++) {
                int idx = tid + i * 256;
                if (idx < 1920) {
                    ((float4*)(smem + NB_HI))[idx] = bh[idx];
                    ((float4*)(smem + NB_LO))[idx] = bl[idx];
                }
            }
        }
        __syncthreads();

        // ---- HMMA: 3 panels ----
        #pragma unroll
        for (int p = 0; p < 3; p++) {
            uint32_t ah0[4], ah1[4], al0[4], al1[4];
            uint32_t ap = aoff + p * PBYTES;
            ldm4(ah0, ap + NA_HI);      ldm4(ah1, ap + NA_HI + 32);
            ldm4(al0, ap + NA_LO);      ldm4(al1, ap + NA_LO + 32);
            #pragma unroll
            for (int g = 0; g < 8; g++) {
                uint32_t bp = boff + p * PBYTES + g * (16 * RSTR);
                uint32_t bh0[4], bh1[4], bl0[4], bl1[4];
                ldm4(bh0, bp + NB_HI);  ldm4(bh1, bp + NB_HI + 32);
                ldm4(bl0, bp + NB_LO);  ldm4(bl1, bp + NB_LO + 32);
                float* c0 = acc + g * 8;
                float* c1 = acc + g * 8 + 4;
                mma16816(c0, ah0, bh0[0], bh0[1]); mma16816(c1, ah0, bh0[2], bh0[3]);
                mma16816(c0, ah1, bh1[0], bh1[1]); mma16816(c1, ah1, bh1[2], bh1[3]);
                mma16816(c0, ah0, bl0[0], bl0[1]); mma16816(c1, ah0, bl0[2], bl0[3]);
                mma16816(c0, ah1, bl1[0], bl1[1]); mma16816(c1, ah1, bl1[2], bl1[3]);
                mma16816(c0, al0, bh0[0], bh0[1]); mma16816(c1, al0, bh0[2], bh0[3]);
                mma16816(c0, al1, bh1[0], bh1[1]); mma16816(c1, al1, bh1[2], bh1[3]);
            }
        }
    }

    // ---- epilogue: bias + relu + pair-exchange -> float4 stores ----
    {
        const int rowA = w * 16 + (l >> 2);
        const int rowB = rowA + 8;
        const int nA = n0 + rowA, nB = n0 + rowB;
        const bool doA = nA < N, doB = nB < N;
        const float* sbias = (const float*)(smem + N_SBIAS);
        #pragma unroll
        for (int G = 0; G < 16; G++) {
            int c0 = G * 8 + (l & 3) * 2;
            float b0 = sbias[c0], b1 = sbias[c0 + 1];
            float v0 = fmaxf(acc[G * 4 + 0] + b0, 0.f);
            float v1 = fmaxf(acc[G * 4 + 1] + b1, 0.f);
            float v2 = fmaxf(acc[G * 4 + 2] + b0, 0.f);
            float v3 = fmaxf(acc[G * 4 + 3] + b1, 0.f);
            float u0 = __shfl_xor_sync(~0u, v0, 1);
            float u1 = __shfl_xor_sync(~0u, v1, 1);
            float u2 = __shfl_xor_sync(~0u, v2, 1);
            float u3 = __shfl_xor_sync(~0u, v3, 1);
            int cb = G * 8 + ((l & 2) << 1);
            if (!(l & 1)) {
                if (doA) *(float4*)(out + (size_t)nA * HID + cb) = make_float4(v0, v1, u0, u1);
            } else {
                if (doB) *(float4*)(out + (size_t)nB * HID + cb) = make_float4(u2, u3, v2, v3);
            }
        }
    }
}

// ---------------------------------------------------------------------------
extern "C" void kernel_launch(void* const* d_in, const int* in_sizes, int n_in,
                              void* d_out, int out_size)
{
    const float* x  = (const float*)d_in[0];
    const int*   ei = (const int*)  d_in[1];
    const float* ea = (const float*)d_in[2];
    const float* Wi = (const float*)d_in[4];
    const float* bi = (const float*)d_in[5];
    // W_h / b_h provably unused: in-loop message cancels exactly (reverse pairs).
    const float* Wo = (const float*)d_in[8];
    const float* bo = (const float*)d_in[9];
    float* out = (float*)d_out;

    const int N = in_sizes[0] / 64;
    const int E = in_sizes[2] / 16;
    const int* src = ei;
    const int* dst = ei + E;

    cudaFuncSetAttribute(k_edge, cudaFuncAttributeMaxDynamicSharedMemorySize, E_SMEM);
    cudaFuncSetAttribute(k_node, cudaFuncAttributeMaxDynamicSharedMemorySize, N_SMEM);

    const int prep_threads = 128 * 96 + 128 * 192;
    k_prep<<<(prep_threads + 255) / 256, 256>>>(Wi, Wo);
    const int n4 = (N * HID) / 4;
    k_zero<<<(n4 + 255) / 256, 256>>>(n4);
    k_edge<<<(E + 127) / 128, 256, E_SMEM>>>(x, src, dst, ea, bi, E);
    k_node<<<(N + 127) / 128, 256, N_SMEM>>>(x, bo, out, N);
}

// round 12
// speedup vs baseline: 1.6048x; 1.6048x over previous
#include <cuda_runtime.h>
#include <cuda_bf16.h>
#include <cstdint>

#define HID 128
#define N_MAX 400000
__device__ float g_M[(size_t)N_MAX * HID];

// Weights pre-arranged in mma.m16n8k16 B-fragment order:
// record idx = (kt*16 + nt)*32 + lane, 16 bytes = {bh0, bh1, bl0, bl1}
// where b0 covers k = kt*16+(lane%4)*2 (+1), b1 covers k+8, n = nt*8 + lane/4.
__device__ __align__(16) unsigned char g_Bfe[5  * 16 * 32 * 16];  // edge W_i  (K=80)
__device__ __align__(16) unsigned char g_Bfn[12 * 16 * 32 * 16];  // node W_o  (K=192)

// ---------------------------------------------------------------------------
// helpers
// ---------------------------------------------------------------------------
__device__ __forceinline__ uint32_t smem_u32(const void* p) {
    uint32_t a;
    asm("{ .reg .u64 t; cvta.to.shared.u64 t, %1; cvt.u32.u64 %0, t; }" : "=r"(a) : "l"(p));
    return a;
}
__device__ __forceinline__ void ldm4(uint32_t* r, uint32_t addr) {
    asm volatile("ldmatrix.sync.aligned.m8n8.x4.shared.b16 {%0,%1,%2,%3}, [%4];"
                 : "=r"(r[0]), "=r"(r[1]), "=r"(r[2]), "=r"(r[3]) : "r"(addr));
}
__device__ __forceinline__ void mma16816(float* c, const uint32_t* a, uint32_t b0, uint32_t b1) {
    asm volatile("mma.sync.aligned.m16n8k16.row.col.f32.bf16.bf16.f32 "
                 "{%0,%1,%2,%3}, {%4,%5,%6,%7}, {%8,%9}, {%0,%1,%2,%3};"
                 : "+f"(c[0]), "+f"(c[1]), "+f"(c[2]), "+f"(c[3])
                 : "r"(a[0]), "r"(a[1]), "r"(a[2]), "r"(a[3]), "r"(b0), "r"(b1));
}
__device__ __forceinline__ void red_add_v4(float* p, float a, float b, float c, float d) {
    asm volatile("red.global.add.v4.f32 [%0], {%1,%2,%3,%4};"
                 :: "l"(p), "f"(a), "f"(b), "f"(c), "f"(d) : "memory");
}
// bf16 split of a float pair -> packed hi/lo bf16x2, memory order [va, vb] (va low)
__device__ __forceinline__ void split2(float va, float vb, uint32_t& hi, uint32_t& lo) {
    uint32_t h;
    asm("cvt.rn.bf16x2.f32 %0, %1, %2;" : "=r"(h) : "f"(vb), "f"(va));
    float ha = __uint_as_float(h << 16);
    float hb = __uint_as_float(h & 0xFFFF0000u);
    float la = va - ha, lb = vb - hb;
    uint32_t l;
    asm("cvt.rn.bf16x2.f32 %0, %1, %2;" : "=r"(l) : "f"(lb), "f"(la));
    hi = h; lo = l;
}
// stage n4 float4s (4 k each) as split bf16 pairs at byte offset `off` (8B per float4)
template<int N4>
__device__ __forceinline__ void stage4(char* aH, char* aL, uint32_t off, const float4* g) {
    #pragma unroll
    for (int j = 0; j < N4; j++) {
        float4 v = g[j];
        uint32_t h, lo;
        split2(v.x, v.y, h, lo);
        *(uint32_t*)(aH + off + j * 8) = h;  *(uint32_t*)(aL + off + j * 8) = lo;
        split2(v.z, v.w, h, lo);
        *(uint32_t*)(aH + off + j * 8 + 4) = h;  *(uint32_t*)(aL + off + j * 8 + 4) = lo;
    }
}

#define RSTRE 176   // edge A row stride: 80 k * 2B + 16B pad (8-phase ldmatrix)
#define RSTRN 400   // node A row stride: 192 k * 2B + 16B pad

// ---------------------------------------------------------------------------
// Kernel P: write weights in B-fragment order (hi/lo split)
// ---------------------------------------------------------------------------
__global__ void k_prep(const float* __restrict__ Wi, const float* __restrict__ Wo) {
    int t = blockIdx.x * blockDim.x + threadIdx.x;
    if (t < 5 * 16 * 32) {
        int l = t & 31, nt = (t >> 5) & 15, kt = t >> 9;
        int n = nt * 8 + (l >> 2), k0 = kt * 16 + (l & 3) * 2;
        float v00 = Wi[k0 * 128 + n],       v01 = Wi[(k0 + 1) * 128 + n];
        float v10 = Wi[(k0 + 8) * 128 + n], v11 = Wi[(k0 + 9) * 128 + n];
        uint32_t h0, l0, h1, l1;
        split2(v00, v01, h0, l0);
        split2(v10, v11, h1, l1);
        ((uint4*)g_Bfe)[t] = make_uint4(h0, h1, l0, l1);
    }
    int t2 = t - 5 * 16 * 32;
    if (t2 >= 0 && t2 < 12 * 16 * 32) {
        int l = t2 & 31, nt = (t2 >> 5) & 15, kt = t2 >> 9;
        int n = nt * 8 + (l >> 2), k0 = kt * 16 + (l & 3) * 2;
        float v00 = Wo[k0 * 128 + n],       v01 = Wo[(k0 + 1) * 128 + n];
        float v10 = Wo[(k0 + 8) * 128 + n], v11 = Wo[(k0 + 9) * 128 + n];
        uint32_t h0, l0, h1, l1;
        split2(v00, v01, h0, l0);
        split2(v10, v11, h1, l1);
        ((uint4*)g_Bfn)[t2] = make_uint4(h0, h1, l0, l1);
    }
}

// ---------------------------------------------------------------------------
// Kernel 0: zero the message buffer
// ---------------------------------------------------------------------------
__global__ void k_zero(int n4) {
    int i = blockIdx.x * blockDim.x + threadIdx.x;
    if (i < n4) ((float4*)g_M)[i] = make_float4(0.f, 0.f, 0.f, 0.f);
}

// ---------------------------------------------------------------------------
// Kernel 1: edges. h0 = relu([x[src]|ea] @ W_i + b_i), scatter M[dst] += h0.
// Tile 64 edges x 128 cols, warp = 16 rows x 64 cols, K=80 (5 k16-tiles).
// ---------------------------------------------------------------------------
#define EA_HI   0
#define EA_LO   11264
#define E_SDST  22528
#define E_SBIAS 22784
#define E_SMEM  23296

__global__ __launch_bounds__(256, 3) void k_edge(
    const float* __restrict__ x,
    const int*   __restrict__ src,
    const int*   __restrict__ dst,
    const float* __restrict__ ea,
    const float* __restrict__ bi,
    int E)
{
    extern __shared__ char smem[];
    const uint32_t sb = smem_u32(smem);
    const int tid = threadIdx.x;
    const int e0 = blockIdx.x * 64;

    // ---- stage A: 4 threads per row, 20 k-floats each ----
    {
        const int row = tid >> 2, p = tid & 3;
        int e = e0 + row;
        int ec = (e < E) ? e : (E - 1);
        int s = src[ec];
        char* aH = smem + EA_HI;
        char* aL = smem + EA_LO;
        uint32_t off = (uint32_t)row * RSTRE + p * 40;   // (p*20 k) * 2B
        if (p < 3) {
            stage4<5>(aH, aL, off, (const float4*)(x + (size_t)s * 64 + p * 20));
        } else {
            stage4<1>(aH, aL, off,      (const float4*)(x + (size_t)s * 64 + 60));
            stage4<4>(aH, aL, off + 8,  (const float4*)(ea + (size_t)ec * 16));
        }
        if (tid < 64) {
            int e2 = e0 + tid;
            ((int*)(smem + E_SDST))[tid] = dst[(e2 < E) ? e2 : (E - 1)];
        }
        if (tid < 128) ((float*)(smem + E_SBIAS))[tid] = bi[tid];
    }
    __syncthreads();

    // ---- mainloop ----
    const int l = tid & 31, w = tid >> 5;
    const int slab = (w >> 1) * 16, ch = w & 1;
    const uint32_t arow = (uint32_t)(slab + ((l >> 3) & 1) * 8 + (l & 7));
    const uint32_t abase = sb + arow * RSTRE + ((l >> 4) << 4);

    float acc[32];
    #pragma unroll
    for (int i = 0; i < 32; i++) acc[i] = 0.f;

    const uint4* __restrict__ Bf = (const uint4*)g_Bfe;

    #pragma unroll
    for (int kt = 0; kt < 5; kt++) {
        uint32_t ah[4], al[4];
        ldm4(ah, abase + EA_HI + kt * 32);
        ldm4(al, abase + EA_LO + kt * 32);
        #pragma unroll
        for (int j = 0; j < 8; j++) {
            uint4 bf = Bf[(size_t)((kt * 16 + ch * 8 + j) * 32 + l)];
            float* c = acc + j * 4;
            mma16816(c, ah, bf.x, bf.y);
            mma16816(c, ah, bf.z, bf.w);
            mma16816(c, al, bf.x, bf.y);
        }
    }

    // ---- epilogue: bias + relu + pair-exchange -> red.v4 scatter ----
    {
        const int rowA = slab + (l >> 2);
        const int rowB = rowA + 8;
        const int dA = ((const int*)(smem + E_SDST))[rowA];
        const int dB = ((const int*)(smem + E_SDST))[rowB];
        const bool doA = (e0 + rowA) < E, doB = (e0 + rowB) < E;
        const float* sbias = (const float*)(smem + E_SBIAS);
        #pragma unroll
        for (int j = 0; j < 8; j++) {
            int c0 = ch * 64 + j * 8 + (l & 3) * 2;
            float b0 = sbias[c0], b1 = sbias[c0 + 1];
            float v0 = fmaxf(acc[j * 4 + 0] + b0, 0.f);
            float v1 = fmaxf(acc[j * 4 + 1] + b1, 0.f);
            float v2 = fmaxf(acc[j * 4 + 2] + b0, 0.f);
            float v3 = fmaxf(acc[j * 4 + 3] + b1, 0.f);
            float u0 = __shfl_xor_sync(~0u, v0, 1);
            float u1 = __shfl_xor_sync(~0u, v1, 1);
            float u2 = __shfl_xor_sync(~0u, v2, 1);
            float u3 = __shfl_xor_sync(~0u, v3, 1);
            int cb = ch * 64 + j * 8 + ((l & 2) << 1);
            if (!(l & 1)) {
                if (doA) red_add_v4(g_M + (size_t)dA * HID + cb, v0, v1, u0, u1);
            } else {
                if (doB) red_add_v4(g_M + (size_t)dB * HID + cb, u2, u3, v2, v3);
            }
        }
    }
}

// ---------------------------------------------------------------------------
// Kernel 2: nodes. out = relu([x|M] @ W_o + b_o).
// Tile 64 nodes x 128 cols, warp = 16 rows x 64 cols, K=192 (12 k16-tiles).
// ---------------------------------------------------------------------------
#define NA_HI   0
#define NA_LO   25600
#define N_SBIAS 51200
#define N_SMEM  51712

__global__ __launch_bounds__(256, 3) void k_node(
    const float* __restrict__ x,
    const float* __restrict__ bo,
    float*       __restrict__ out,
    int N)
{
    extern __shared__ char smem[];
    const uint32_t sb = smem_u32(smem);
    const int tid = threadIdx.x;
    const int n0 = blockIdx.x * 64;

    // ---- stage A: 4 threads per row, 48 k-floats each (concat [x | M]) ----
    {
        const int row = tid >> 2, p = tid & 3;
        int n = n0 + row;
        int nc = (n < N) ? n : (N - 1);
        char* aH = smem + NA_HI;
        char* aL = smem + NA_LO;
        uint32_t off = (uint32_t)row * RSTRN + p * 96;   // (p*48 k) * 2B
        const float* xr = x + (size_t)nc * 64;
        const float* mr = g_M + (size_t)nc * HID;
        if (p == 0) {
            stage4<12>(aH, aL, off, (const float4*)xr);
        } else if (p == 1) {
            stage4<4>(aH, aL, off,      (const float4*)(xr + 48));
            stage4<8>(aH, aL, off + 32, (const float4*)mr);
        } else if (p == 2) {
            stage4<12>(aH, aL, off, (const float4*)(mr + 32));
        } else {
            stage4<12>(aH, aL, off, (const float4*)(mr + 80));
        }
        if (tid < 128) ((float*)(smem + N_SBIAS))[tid] = bo[tid];
    }
    __syncthreads();

    // ---- mainloop ----
    const int l = tid & 31, w = tid >> 5;
    const int slab = (w >> 1) * 16, ch = w & 1;
    const uint32_t arow = (uint32_t)(slab + ((l >> 3) & 1) * 8 + (l & 7));
    const uint32_t abase = sb + arow * RSTRN + ((l >> 4) << 4);

    float acc[32];
    #pragma unroll
    for (int i = 0; i < 32; i++) acc[i] = 0.f;

    const uint4* __restrict__ Bf = (const uint4*)g_Bfn;

    #pragma unroll 2
    for (int kt = 0; kt < 12; kt++) {
        uint32_t ah[4], al[4];
        ldm4(ah, abase + NA_HI + kt * 32);
        ldm4(al, abase + NA_LO + kt * 32);
        #pragma unroll
        for (int j = 0; j < 8; j++) {
            uint4 bf = Bf[(size_t)((kt * 16 + ch * 8 + j) * 32 + l)];
            float* c = acc + j * 4;
            mma16816(c, ah, bf.x, bf.y);
            mma16816(c, ah, bf.z, bf.w);
            mma16816(c, al, bf.x, bf.y);
        }
    }

    // ---- epilogue: bias + relu + pair-exchange -> float4 stores ----
    {
        const int rowA = slab + (l >> 2);
        const int rowB = rowA + 8;
        const int nA = n0 + rowA, nB = n0 + rowB;
        const bool doA = nA < N, doB = nB < N;
        const float* sbias = (const float*)(smem + N_SBIAS);
        #pragma unroll
        for (int j = 0; j < 8; j++) {
            int c0 = ch * 64 + j * 8 + (l & 3) * 2;
            float b0 = sbias[c0], b1 = sbias[c0 + 1];
            float v0 = fmaxf(acc[j * 4 + 0] + b0, 0.f);
            float v1 = fmaxf(acc[j * 4 + 1] + b1, 0.f);
            float v2 = fmaxf(acc[j * 4 + 2] + b0, 0.f);
            float v3 = fmaxf(acc[j * 4 + 3] + b1, 0.f);
            float u0 = __shfl_xor_sync(~0u, v0, 1);
            float u1 = __shfl_xor_sync(~0u, v1, 1);
            float u2 = __shfl_xor_sync(~0u, v2, 1);
            float u3 = __shfl_xor_sync(~0u, v3, 1);
            int cb = ch * 64 + j * 8 + ((l & 2) << 1);
            if (!(l & 1)) {
                if (doA) *(float4*)(out + (size_t)nA * HID + cb) = make_float4(v0, v1, u0, u1);
            } else {
                if (doB) *(float4*)(out + (size_t)nB * HID + cb) = make_float4(u2, u3, v2, v3);
            }
        }
    }
}

// ---------------------------------------------------------------------------
extern "C" void kernel_launch(void* const* d_in, const int* in_sizes, int n_in,
                              void* d_out, int out_size)
{
    const float* x  = (const float*)d_in[0];
    const int*   ei = (const int*)  d_in[1];
    const float* ea = (const float*)d_in[2];
    const float* Wi = (const float*)d_in[4];
    const float* bi = (const float*)d_in[5];
    // W_h / b_h provably unused: in-loop message cancels exactly (reverse pairs).
    const float* Wo = (const float*)d_in[8];
    const float* bo = (const float*)d_in[9];
    float* out = (float*)d_out;

    const int N = in_sizes[0] / 64;
    const int E = in_sizes[2] / 16;
    const int* src = ei;
    const int* dst = ei + E;

    cudaFuncSetAttribute(k_node, cudaFuncAttributeMaxDynamicSharedMemorySize, N_SMEM);

    const int prep_threads = (5 + 12) * 16 * 32;
    k_prep<<<(prep_threads + 255) / 256, 256>>>(Wi, Wo);
    const int n4 = (N * HID) / 4;
    k_zero<<<(n4 + 255) / 256, 256>>>(n4);
    k_edge<<<(E + 63) / 64, 256, E_SMEM>>>(x, src, dst, ea, bi, E);
    k_node<<<(N + 63) / 64, 256, N_SMEM>>>(x, bo, out, N);
}

// round 13
// speedup vs baseline: 1.8677x; 1.1638x over previous
#include <cuda_runtime.h>
#include <cuda_bf16.h>
#include <cstdint>

#define HID 128
#define N_MAX 400000
__device__ float g_M[(size_t)N_MAX * HID];

// Weights pre-arranged in mma.m16n8k16 B-fragment order:
// record idx = (kt*16 + nt)*32 + lane, 16 bytes = {bh0, bh1, bl0, bl1}
// where b0 covers k = kt*16+(lane%4)*2 (+1), b1 covers k+8, n = nt*8 + lane/4.
__device__ __align__(16) unsigned char g_Bfe[5  * 16 * 32 * 16];  // edge W_i  (K=80)
__device__ __align__(16) unsigned char g_Bfn[12 * 16 * 32 * 16];  // node W_o  (K=192)

// ---------------------------------------------------------------------------
// helpers
// ---------------------------------------------------------------------------
__device__ __forceinline__ uint32_t smem_u32(const void* p) {
    uint32_t a;
    asm("{ .reg .u64 t; cvta.to.shared.u64 t, %1; cvt.u32.u64 %0, t; }" : "=r"(a) : "l"(p));
    return a;
}
__device__ __forceinline__ void ldm4(uint32_t* r, uint32_t addr) {
    asm volatile("ldmatrix.sync.aligned.m8n8.x4.shared.b16 {%0,%1,%2,%3}, [%4];"
                 : "=r"(r[0]), "=r"(r[1]), "=r"(r[2]), "=r"(r[3]) : "r"(addr));
}
__device__ __forceinline__ void mma16816(float* c, const uint32_t* a, uint32_t b0, uint32_t b1) {
    asm volatile("mma.sync.aligned.m16n8k16.row.col.f32.bf16.bf16.f32 "
                 "{%0,%1,%2,%3}, {%4,%5,%6,%7}, {%8,%9}, {%0,%1,%2,%3};"
                 : "+f"(c[0]), "+f"(c[1]), "+f"(c[2]), "+f"(c[3])
                 : "r"(a[0]), "r"(a[1]), "r"(a[2]), "r"(a[3]), "r"(b0), "r"(b1));
}
__device__ __forceinline__ void red_add_v4(float* p, float a, float b, float c, float d) {
    asm volatile("red.global.add.v4.f32 [%0], {%1,%2,%3,%4};"
                 :: "l"(p), "f"(a), "f"(b), "f"(c), "f"(d) : "memory");
}
// bf16 split of a float pair -> packed hi/lo bf16x2, memory order [va, vb] (va low)
__device__ __forceinline__ void split2(float va, float vb, uint32_t& hi, uint32_t& lo) {
    uint32_t h;
    asm("cvt.rn.bf16x2.f32 %0, %1, %2;" : "=r"(h) : "f"(vb), "f"(va));
    float ha = __uint_as_float(h << 16);
    float hb = __uint_as_float(h & 0xFFFF0000u);
    float la = va - ha, lb = vb - hb;
    uint32_t l;
    asm("cvt.rn.bf16x2.f32 %0, %1, %2;" : "=r"(l) : "f"(lb), "f"(la));
    hi = h; lo = l;
}
// stage n4 float4s (4 k each) as split bf16 pairs at byte offset `off` (8B per float4)
template<int N4>
__device__ __forceinline__ void stage4(char* aH, char* aL, uint32_t off, const float4* g) {
    #pragma unroll
    for (int j = 0; j < N4; j++) {
        float4 v = g[j];
        uint32_t h, lo;
        split2(v.x, v.y, h, lo);
        *(uint32_t*)(aH + off + j * 8) = h;  *(uint32_t*)(aL + off + j * 8) = lo;
        split2(v.z, v.w, h, lo);
        *(uint32_t*)(aH + off + j * 8 + 4) = h;  *(uint32_t*)(aL + off + j * 8 + 4) = lo;
    }
}

#define RSTRE 176   // edge A row stride: 80 k * 2B + 16B pad (8-phase ldmatrix)
#define RSTRN 400   // node A row stride: 192 k * 2B + 16B pad

// ---------------------------------------------------------------------------
// Kernel P: write weights in B-fragment order (hi/lo split)
// ---------------------------------------------------------------------------
__global__ void k_prep(const float* __restrict__ Wi, const float* __restrict__ Wo) {
    int t = blockIdx.x * blockDim.x + threadIdx.x;
    if (t < 5 * 16 * 32) {
        int l = t & 31, nt = (t >> 5) & 15, kt = t >> 9;
        int n = nt * 8 + (l >> 2), k0 = kt * 16 + (l & 3) * 2;
        float v00 = Wi[k0 * 128 + n],       v01 = Wi[(k0 + 1) * 128 + n];
        float v10 = Wi[(k0 + 8) * 128 + n], v11 = Wi[(k0 + 9) * 128 + n];
        uint32_t h0, l0, h1, l1;
        split2(v00, v01, h0, l0);
        split2(v10, v11, h1, l1);
        ((uint4*)g_Bfe)[t] = make_uint4(h0, h1, l0, l1);
    }
    int t2 = t - 5 * 16 * 32;
    if (t2 >= 0 && t2 < 12 * 16 * 32) {
        int l = t2 & 31, nt = (t2 >> 5) & 15, kt = t2 >> 9;
        int n = nt * 8 + (l >> 2), k0 = kt * 16 + (l & 3) * 2;
        float v00 = Wo[k0 * 128 + n],       v01 = Wo[(k0 + 1) * 128 + n];
        float v10 = Wo[(k0 + 8) * 128 + n], v11 = Wo[(k0 + 9) * 128 + n];
        uint32_t h0, l0, h1, l1;
        split2(v00, v01, h0, l0);
        split2(v10, v11, h1, l1);
        ((uint4*)g_Bfn)[t2] = make_uint4(h0, h1, l0, l1);
    }
}

// ---------------------------------------------------------------------------
// Kernel 0: zero the message buffer
// ---------------------------------------------------------------------------
__global__ void k_zero(int n4) {
    int i = blockIdx.x * blockDim.x + threadIdx.x;
    if (i < n4) ((float4*)g_M)[i] = make_float4(0.f, 0.f, 0.f, 0.f);
}

// ---------------------------------------------------------------------------
// Kernel 1: edges. h0 = relu([x[src]|ea] @ W_i + b_i), scatter M[dst] += h0.
// CTA = 128 threads, 64 edges; warp = 32 rows x 64 cols; K=80 (5 k16-tiles).
// Each B fragment now feeds 6 MMAs (32 rows), halving B L1 traffic.
// ---------------------------------------------------------------------------
#define EA_HI   0
#define EA_LO   11264
#define E_SDST  22528
#define E_SBIAS 22784
#define E_SMEM  23296

__global__ __launch_bounds__(128, 4) void k_edge(
    const float* __restrict__ x,
    const int*   __restrict__ src,
    const int*   __restrict__ dst,
    const float* __restrict__ ea,
    const float* __restrict__ bi,
    int E)
{
    extern __shared__ char smem[];
    const uint32_t sb = smem_u32(smem);
    const int tid = threadIdx.x;
    const int e0 = blockIdx.x * 64;

    // ---- stage A: 2 threads per row, 40 k-floats each ----
    {
        const int row = tid >> 1, p = tid & 1;
        int e = e0 + row;
        int ec = (e < E) ? e : (E - 1);
        int s = src[ec];
        char* aH = smem + EA_HI;
        char* aL = smem + EA_LO;
        uint32_t off = (uint32_t)row * RSTRE + p * 80;   // (p*40 k) * 2B
        if (p == 0) {
            stage4<10>(aH, aL, off, (const float4*)(x + (size_t)s * 64));
        } else {
            stage4<6>(aH, aL, off,      (const float4*)(x + (size_t)s * 64 + 40));
            stage4<4>(aH, aL, off + 48, (const float4*)(ea + (size_t)ec * 16));
        }
        if (tid < 64) {
            int e2 = e0 + tid;
            ((int*)(smem + E_SDST))[tid] = dst[(e2 < E) ? e2 : (E - 1)];
        }
        ((float*)(smem + E_SBIAS))[tid] = bi[tid];
    }
    __syncthreads();

    // ---- mainloop ----
    const int l = tid & 31, w = tid >> 5;
    const int slab = (w >> 1) * 32, ch = w & 1;
    const uint32_t arow = (uint32_t)(slab + ((l >> 3) & 1) * 8 + (l & 7));
    const uint32_t a0 = sb + arow * RSTRE + ((l >> 4) << 4);
    const uint32_t a1 = a0 + 16 * RSTRE;

    float acc[64];
    #pragma unroll
    for (int i = 0; i < 64; i++) acc[i] = 0.f;

    const uint4* __restrict__ Bf = (const uint4*)g_Bfe;

    #pragma unroll
    for (int kt = 0; kt < 5; kt++) {
        uint32_t ah0[4], ah1[4], al0[4], al1[4];
        ldm4(ah0, a0 + EA_HI + kt * 32);
        ldm4(ah1, a1 + EA_HI + kt * 32);
        ldm4(al0, a0 + EA_LO + kt * 32);
        ldm4(al1, a1 + EA_LO + kt * 32);
        #pragma unroll
        for (int j = 0; j < 8; j++) {
            uint4 bf = Bf[(size_t)((kt * 16 + ch * 8 + j) * 32 + l)];
            float* c0 = acc + j * 8;
            float* c1 = acc + j * 8 + 4;
            mma16816(c0, ah0, bf.x, bf.y);  mma16816(c1, ah1, bf.x, bf.y);
            mma16816(c0, ah0, bf.z, bf.w);  mma16816(c1, ah1, bf.z, bf.w);
            mma16816(c0, al0, bf.x, bf.y);  mma16816(c1, al1, bf.x, bf.y);
        }
    }

    // ---- epilogue: bias + relu + pair-exchange -> red.v4 scatter (4 rows) ----
    {
        const int r0 = slab + (l >> 2);
        const int* sdst = (const int*)(smem + E_SDST);
        const int dr[4] = { sdst[r0], sdst[r0 + 8], sdst[r0 + 16], sdst[r0 + 24] };
        const bool dok[4] = { (e0 + r0) < E, (e0 + r0 + 8) < E,
                              (e0 + r0 + 16) < E, (e0 + r0 + 24) < E };
        const float* sbias = (const float*)(smem + E_SBIAS);
        #pragma unroll
        for (int j = 0; j < 8; j++) {
            int c0 = ch * 64 + j * 8 + (l & 3) * 2;
            float b0 = sbias[c0], b1 = sbias[c0 + 1];
            int cb = ch * 64 + j * 8 + ((l & 2) << 1);
            #pragma unroll
            for (int h = 0; h < 2; h++) {   // h=0: rows r0/r0+8 ; h=1: +16/+24
                float v0 = fmaxf(acc[j * 8 + h * 4 + 0] + b0, 0.f);
                float v1 = fmaxf(acc[j * 8 + h * 4 + 1] + b1, 0.f);
                float v2 = fmaxf(acc[j * 8 + h * 4 + 2] + b0, 0.f);
                float v3 = fmaxf(acc[j * 8 + h * 4 + 3] + b1, 0.f);
                float u0 = __shfl_xor_sync(~0u, v0, 1);
                float u1 = __shfl_xor_sync(~0u, v1, 1);
                float u2 = __shfl_xor_sync(~0u, v2, 1);
                float u3 = __shfl_xor_sync(~0u, v3, 1);
                if (!(l & 1)) {
                    if (dok[h * 2])
                        red_add_v4(g_M + (size_t)dr[h * 2] * HID + cb, v0, v1, u0, u1);
                } else {
                    if (dok[h * 2 + 1])
                        red_add_v4(g_M + (size_t)dr[h * 2 + 1] * HID + cb, u2, u3, v2, v3);
                }
            }
        }
    }
}

// ---------------------------------------------------------------------------
// Kernel 2: nodes. out = relu([x|M] @ W_o + b_o).
// CTA = 128 threads, 64 nodes; warp = 32 rows x 64 cols; K=192 (12 k16-tiles).
// ---------------------------------------------------------------------------
#define NA_HI   0
#define NA_LO   25600
#define N_SBIAS 51200
#define N_SMEM  51712

__global__ __launch_bounds__(128, 4) void k_node(
    const float* __restrict__ x,
    const float* __restrict__ bo,
    float*       __restrict__ out,
    int N)
{
    extern __shared__ char smem[];
    const uint32_t sb = smem_u32(smem);
    const int tid = threadIdx.x;
    const int n0 = blockIdx.x * 64;

    // ---- stage A: 2 threads per row, 96 k-floats each (concat [x | M]) ----
    {
        const int row = tid >> 1, p = tid & 1;
        int n = n0 + row;
        int nc = (n < N) ? n : (N - 1);
        char* aH = smem + NA_HI;
        char* aL = smem + NA_LO;
        uint32_t off = (uint32_t)row * RSTRN + p * 192;   // (p*96 k) * 2B
        const float* xr = x + (size_t)nc * 64;
        const float* mr = g_M + (size_t)nc * HID;
        if (p == 0) {
            stage4<16>(aH, aL, off,       (const float4*)xr);
            stage4<8>(aH, aL, off + 128, (const float4*)mr);
        } else {
            stage4<24>(aH, aL, off, (const float4*)(mr + 32));
        }
        ((float*)(smem + N_SBIAS))[tid] = bo[tid];
    }
    __syncthreads();

    // ---- mainloop ----
    const int l = tid & 31, w = tid >> 5;
    const int slab = (w >> 1) * 32, ch = w & 1;
    const uint32_t arow = (uint32_t)(slab + ((l >> 3) & 1) * 8 + (l & 7));
    const uint32_t a0 = sb + arow * RSTRN + ((l >> 4) << 4);
    const uint32_t a1 = a0 + 16 * RSTRN;

    float acc[64];
    #pragma unroll
    for (int i = 0; i < 64; i++) acc[i] = 0.f;

    const uint4* __restrict__ Bf = (const uint4*)g_Bfn;

    #pragma unroll 2
    for (int kt = 0; kt < 12; kt++) {
        uint32_t ah0[4], ah1[4], al0[4], al1[4];
        ldm4(ah0, a0 + NA_HI + kt * 32);
        ldm4(ah1, a1 + NA_HI + kt * 32);
        ldm4(al0, a0 + NA_LO + kt * 32);
        ldm4(al1, a1 + NA_LO + kt * 32);
        #pragma unroll
        for (int j = 0; j < 8; j++) {
            uint4 bf = Bf[(size_t)((kt * 16 + ch * 8 + j) * 32 + l)];
            float* c0 = acc + j * 8;
            float* c1 = acc + j * 8 + 4;
            mma16816(c0, ah0, bf.x, bf.y);  mma16816(c1, ah1, bf.x, bf.y);
            mma16816(c0, ah0, bf.z, bf.w);  mma16816(c1, ah1, bf.z, bf.w);
            mma16816(c0, al0, bf.x, bf.y);  mma16816(c1, al1, bf.x, bf.y);
        }
    }

    // ---- epilogue: bias + relu + pair-exchange -> float4 stores (4 rows) ----
    {
        const int r0 = slab + (l >> 2);
        const int nr[4] = { n0 + r0, n0 + r0 + 8, n0 + r0 + 16, n0 + r0 + 24 };
        const bool dok[4] = { nr[0] < N, nr[1] < N, nr[2] < N, nr[3] < N };
        const float* sbias = (const float*)(smem + N_SBIAS);
        #pragma unroll
        for (int j = 0; j < 8; j++) {
            int c0 = ch * 64 + j * 8 + (l & 3) * 2;
            float b0 = sbias[c0], b1 = sbias[c0 + 1];
            int cb = ch * 64 + j * 8 + ((l & 2) << 1);
            #pragma unroll
            for (int h = 0; h < 2; h++) {
                float v0 = fmaxf(acc[j * 8 + h * 4 + 0] + b0, 0.f);
                float v1 = fmaxf(acc[j * 8 + h * 4 + 1] + b1, 0.f);
                float v2 = fmaxf(acc[j * 8 + h * 4 + 2] + b0, 0.f);
                float v3 = fmaxf(acc[j * 8 + h * 4 + 3] + b1, 0.f);
                float u0 = __shfl_xor_sync(~0u, v0, 1);
                float u1 = __shfl_xor_sync(~0u, v1, 1);
                float u2 = __shfl_xor_sync(~0u, v2, 1);
                float u3 = __shfl_xor_sync(~0u, v3, 1);
                if (!(l & 1)) {
                    if (dok[h * 2])
                        *(float4*)(out + (size_t)nr[h * 2] * HID + cb) = make_float4(v0, v1, u0, u1);
                } else {
                    if (dok[h * 2 + 1])
                        *(float4*)(out + (size_t)nr[h * 2 + 1] * HID + cb) = make_float4(u2, u3, v2, v3);
                }
            }
        }
    }
}

// ---------------------------------------------------------------------------
extern "C" void kernel_launch(void* const* d_in, const int* in_sizes, int n_in,
                              void* d_out, int out_size)
{
    const float* x  = (const float*)d_in[0];
    const int*   ei = (const int*)  d_in[1];
    const float* ea = (const float*)d_in[2];
    const float* Wi = (const float*)d_in[4];
    const float* bi = (const float*)d_in[5];
    // W_h / b_h provably unused: in-loop message cancels exactly (reverse pairs).
    const float* Wo = (const float*)d_in[8];
    const float* bo = (const float*)d_in[9];
    float* out = (float*)d_out;

    const int N = in_sizes[0] / 64;
    const int E = in_sizes[2] / 16;
    const int* src = ei;
    const int* dst = ei + E;

    cudaFuncSetAttribute(k_node, cudaFuncAttributeMaxDynamicSharedMemorySize, N_SMEM);

    const int prep_threads = (5 + 12) * 16 * 32;
    k_prep<<<(prep_threads + 255) / 256, 256>>>(Wi, Wo);
    const int n4 = (N * HID) / 4;
    k_zero<<<(n4 + 255) / 256, 256>>>(n4);
    k_edge<<<(E + 63) / 64, 128, E_SMEM>>>(x, src, dst, ea, bi, E);
    k_node<<<(N + 63) / 64, 128, N_SMEM>>>(x, bo, out, N);
}